// round 12
// baseline (speedup 1.0000x reference)
#include <cuda_runtime.h>
#include <cstdint>

// Problem constants
#define CB 4
#define CT 2048
#define CD 2048
#define CH 16
#define CHD 128
#define QKVD (3 * CD)   // 6144

// Scratch (allocation-free rule: __device__ globals)
__device__ float g_qkv[(size_t)CB * CT * QKVD];   // [b, t, 6144]  (q | k | v), tf32-rounded
__device__ float g_y[(size_t)CB * CT * CD];       // [b, t, h*128+hd], tf32-rounded
__device__ float g_xt[(size_t)CB * CT * CD];      // x, tf32-rounded
__device__ float g_wqkvt[(size_t)QKVD * CD];      // w_qkv, tf32-rounded
__device__ float g_wot[(size_t)CD * CD];          // w_o, tf32-rounded

__device__ __forceinline__ uint32_t f2tf32(float f) {
    uint32_t r;
    asm("cvt.rna.tf32.f32 %0, %1;" : "=r"(r) : "f"(f));
    return r;
}
__device__ __forceinline__ float rtf(float f) {
    return __uint_as_float(f2tf32(f));
}

__device__ __forceinline__ float ex2(float x) {
    float r;
    asm("ex2.approx.f32 %0, %1;" : "=f"(r) : "f"(x));
    return r;
}

__device__ __forceinline__ void mma_tf32(
    float& c0, float& c1, float& c2, float& c3,
    uint32_t a0, uint32_t a1, uint32_t a2, uint32_t a3,
    uint32_t b0, uint32_t b1)
{
    asm volatile(
        "mma.sync.aligned.m16n8k8.row.col.f32.tf32.tf32.f32 "
        "{%0,%1,%2,%3}, {%4,%5,%6,%7}, {%8,%9}, {%0,%1,%2,%3};"
        : "+f"(c0), "+f"(c1), "+f"(c2), "+f"(c3)
        : "r"(a0), "r"(a1), "r"(a2), "r"(a3), "r"(b0), "r"(b1));
}

__device__ __forceinline__ void ldsm_x4(
    uint32_t& r0, uint32_t& r1, uint32_t& r2, uint32_t& r3, uint32_t addr)
{
    asm volatile(
        "ldmatrix.sync.aligned.m8n8.x4.shared.b16 {%0,%1,%2,%3}, [%4];"
        : "=r"(r0), "=r"(r1), "=r"(r2), "=r"(r3) : "r"(addr));
}

__device__ __forceinline__ void cp16(uint32_t smem, const void* gmem) {
    asm volatile("cp.async.cg.shared.global [%0], [%1], 16;"
                 :: "r"(smem), "l"(gmem));
}
__device__ __forceinline__ void cp_commit() {
    asm volatile("cp.async.commit_group;");
}
template <int N>
__device__ __forceinline__ void cp_wait() {
    asm volatile("cp.async.wait_group %0;" :: "n"(N));
}

// Per-lane byte offset for an A-fragment ldmatrix (m16 x k8 tile)
__device__ __forceinline__ uint32_t a_lane_off(int lane, int strideW) {
    return (uint32_t)((((lane & 7) + ((lane >> 3) & 1) * 8) * strideW
                       + (lane >> 4) * 4) * 4);
}
// Per-lane byte offset for a B-fragment ldmatrix covering 2 n8 tiles
__device__ __forceinline__ uint32_t b_lane_off(int lane, int strideW) {
    return (uint32_t)(((((lane >> 4) & 1) * 8 + (lane & 7)) * strideW
                       + ((lane >> 3) & 1) * 4) * 4);
}

// ---------------------------------------------------------------------------
// Elementwise tf32 rounding: out[i] = round_rna_tf32(in[i])
// ---------------------------------------------------------------------------
__global__ __launch_bounds__(256) void round_tf32_kernel(
    const float4* __restrict__ in, float4* __restrict__ out, int n4)
{
    int i = blockIdx.x * blockDim.x + threadIdx.x;
    if (i < n4) {
        float4 v = in[i];
        out[i] = make_float4(rtf(v.x), rtf(v.y), rtf(v.z), rtf(v.w));
    }
}

// ===========================================================================
// Tensor-core (mma.sync tf32) NT GEMM: C[M,N] = A[M,K] @ B[N,K]^T
// Inputs must be PRE-ROUNDED to tf32 in gmem.
// CTA tile 128x256, BK=16, 256 threads = 8 warps (2 m x 4 n), warp tile 64x64.
// 3-stage cp.async pipeline, ldmatrix fragment loads.
// roundC != 0 -> epilogue rounds outputs to tf32 (for chained GEMM consumers).
// ===========================================================================
#define SAST 20
#define A_BUF_W (128 * SAST)            // words per A buffer (2560)
#define B_BUF_W (256 * SAST)            // words per B buffer (5120)
#define NSTAGE 3
#define SGEMM_SMEM_BYTES ((NSTAGE * A_BUF_W + NSTAGE * B_BUF_W) * 4)  // 92160

__global__ __launch_bounds__(256, 1) void sgemm_tc(
    const float* __restrict__ A, const float* __restrict__ Bm,
    float* __restrict__ C, int M, int N, int K, int roundC)
{
    extern __shared__ uint32_t smw[];
    uint32_t* As = smw;                          // [NSTAGE][A_BUF_W]
    uint32_t* Bs = smw + NSTAGE * A_BUF_W;       // [NSTAGE][B_BUF_W]

    const int tid = threadIdx.x;
    const int wid = tid >> 5;
    const int lane = tid & 31;
    const int g = lane >> 2;      // 0..7
    const int q = lane & 3;       // 0..3

    const int warp_m = wid & 1;           // 0..1 -> m offset *64
    const int warp_n = wid >> 1;          // 0..3 -> n offset *64

    const int rowBase = blockIdx.y * 128;
    const int colBase = blockIdx.x * 256;

    // Global loaders: row = tid>>2 (+64k), col4 = tid&3
    const int lrow = tid >> 2;            // 0..63
    const int lc4 = (tid & 3) * 4;        // 0,4,8,12
    const float* Ap0 = A + (size_t)(rowBase + lrow) * K + lc4;
    const float* Ap1 = Ap0 + (size_t)64 * K;
    const float* Bp0 = Bm + (size_t)(colBase + lrow) * K + lc4;
    const float* Bp1 = Bp0 + (size_t)64 * K;
    const float* Bp2 = Bp0 + (size_t)128 * K;
    const float* Bp3 = Bp0 + (size_t)192 * K;

    const uint32_t aSm = (uint32_t)__cvta_generic_to_shared(As);
    const uint32_t bSm = (uint32_t)__cvta_generic_to_shared(Bs);
    const uint32_t stDst = (uint32_t)((lrow * SAST + lc4) * 4);
    const uint32_t aFrag0 = aSm + a_lane_off(lane, SAST)
                          + (uint32_t)(warp_m * 64 * SAST * 4);
    const uint32_t bFrag0 = bSm + b_lane_off(lane, SAST)
                          + (uint32_t)(warp_n * 64 * SAST * 4);

    float acc[4][8][4];
#pragma unroll
    for (int mt = 0; mt < 4; mt++)
#pragma unroll
        for (int nt = 0; nt < 8; nt++)
#pragma unroll
            for (int c = 0; c < 4; c++) acc[mt][nt][c] = 0.0f;

    const int nstages = K >> 4;   // K/16

    // Issue stage st's copies into ring buffer st % NSTAGE
    auto issue = [&](int st) {
        const int koff = st << 4;
        const int buf = st % NSTAGE;
        const uint32_t aO = aSm + (uint32_t)(buf * A_BUF_W * 4) + stDst;
        const uint32_t bO = bSm + (uint32_t)(buf * B_BUF_W * 4) + stDst;
        cp16(aO,                                Ap0 + koff);
        cp16(aO + (uint32_t)(64 * SAST * 4),    Ap1 + koff);
        cp16(bO,                                Bp0 + koff);
        cp16(bO + (uint32_t)(64 * SAST * 4),    Bp1 + koff);
        cp16(bO + (uint32_t)(128 * SAST * 4),   Bp2 + koff);
        cp16(bO + (uint32_t)(192 * SAST * 4),   Bp3 + koff);
        cp_commit();
    };

    // Prologue: stages 0 and 1 in flight
    issue(0);
    issue(1);

    for (int s = 0; s < nstages; s++) {
        // Wait for stage s to land, then make visible to all warps
        if (s < nstages - 2) cp_wait<1>();
        else                 cp_wait<0>();
        __syncthreads();

        // Issue stage s+2 (overwrites buffer of stage s-1; all warps passed
        // its compute before the sync above)
        if (s + 2 < nstages) issue(s + 2);

        const int buf = s % NSTAGE;
        const uint32_t aOff = (uint32_t)(buf * A_BUF_W * 4);
        const uint32_t bOff = (uint32_t)(buf * B_BUF_W * 4);

#pragma unroll
        for (int kk = 0; kk < 16; kk += 8) {
            uint32_t afr[4][4];
#pragma unroll
            for (int mt = 0; mt < 4; mt++)
                ldsm_x4(afr[mt][0], afr[mt][1], afr[mt][2], afr[mt][3],
                        aFrag0 + aOff
                        + (uint32_t)((mt * 16 * SAST + kk) * 4));
#pragma unroll
            for (int ntp = 0; ntp < 4; ntp++) {
                uint32_t b0, b1, b2, b3;
                ldsm_x4(b0, b1, b2, b3,
                        bFrag0 + bOff
                        + (uint32_t)((ntp * 16 * SAST + kk) * 4));
#pragma unroll
                for (int mt = 0; mt < 4; mt++) {
                    mma_tf32(acc[mt][2 * ntp][0], acc[mt][2 * ntp][1],
                             acc[mt][2 * ntp][2], acc[mt][2 * ntp][3],
                             afr[mt][0], afr[mt][1], afr[mt][2], afr[mt][3],
                             b0, b1);
                    mma_tf32(acc[mt][2 * ntp + 1][0], acc[mt][2 * ntp + 1][1],
                             acc[mt][2 * ntp + 1][2], acc[mt][2 * ntp + 1][3],
                             afr[mt][0], afr[mt][1], afr[mt][2], afr[mt][3],
                             b2, b3);
                }
            }
        }
        __syncthreads();   // all warps done with buffer s before it is refilled
    }

    // Epilogue
#pragma unroll
    for (int mt = 0; mt < 4; mt++) {
        const int m0 = rowBase + warp_m * 64 + mt * 16;
#pragma unroll
        for (int nt = 0; nt < 8; nt++) {
            const int n0 = colBase + warp_n * 64 + nt * 8;
            float v0 = acc[mt][nt][0], v1 = acc[mt][nt][1];
            float v2 = acc[mt][nt][2], v3 = acc[mt][nt][3];
            if (roundC) { v0 = rtf(v0); v1 = rtf(v1); v2 = rtf(v2); v3 = rtf(v3); }
            *(float2*)(C + (size_t)(m0 + g) * N + n0 + 2 * q) = make_float2(v0, v1);
            *(float2*)(C + (size_t)(m0 + g + 8) * N + n0 + 2 * q) = make_float2(v2, v3);
        }
    }
}

// ===========================================================================
// Tensor-core flash attention (tf32 mma, online softmax, exp2 domain).
// qkv is PRE-ROUNDED tf32; epilogue writes y tf32-rounded for the O-proj GEMM.
// ===========================================================================
#define FQ 128
#define FKT 64
#define QST 132
#define PST 68
#define VTST 68

#define FLASH_SMEM_FLOATS (FQ * QST + FKT * QST + CHD * VTST + FQ * PST + FKT)
#define FLASH_SMEM_BYTES (FLASH_SMEM_FLOATS * 4)

__global__ __launch_bounds__(256, 1) void flash_attn_tc(
    const float* __restrict__ qkv, const int* __restrict__ mask,
    float* __restrict__ y)
{
    extern __shared__ uint32_t smu[];
    uint32_t* Qs = smu;                       // FQ x QST (tf32 bits)
    uint32_t* Ks = Qs + FQ * QST;             // FKT x QST
    uint32_t* Vt = Ks + FKT * QST;            // CHD x VTST (transposed V)
    uint32_t* Ps = Vt + CHD * VTST;           // FQ x PST
    float* bias = (float*)(Ps + FQ * PST);    // FKT

    const int qt = blockIdx.x;                // 0..15
    const int bh = blockIdx.y;                // 0..63
    const int b = bh / CH;
    const int h = bh % CH;

    const int tid = threadIdx.x;
    const int wid = tid >> 5;                 // 0..7
    const int lane = tid & 31;
    const int g = lane >> 2;                  // 0..7
    const int q = lane & 3;                   // 0..3
    const int m0 = wid * 16;                  // warp's query-row base

    const size_t baseQ = (size_t)b * CT * QKVD + (size_t)h * CHD;
    const size_t baseK = baseQ + CD;
    const size_t baseV = baseQ + 2 * CD;
    const int q0 = qt * FQ;

    const uint32_t qSm = (uint32_t)__cvta_generic_to_shared(Qs);
    const uint32_t kSm = (uint32_t)__cvta_generic_to_shared(Ks);
    const uint32_t vSm = (uint32_t)__cvta_generic_to_shared(Vt);
    const uint32_t pSm = (uint32_t)__cvta_generic_to_shared(Ps);

    const uint32_t aQ = qSm + a_lane_off(lane, QST) + (uint32_t)(m0 * QST * 4);
    const uint32_t bK = kSm + b_lane_off(lane, QST);
    const uint32_t aP = pSm + a_lane_off(lane, PST) + (uint32_t)(m0 * PST * 4);
    const uint32_t bV = vSm + b_lane_off(lane, VTST);

    // Load Q tile (scaled by 1/sqrt(HD) * log2(e), re-rounded to tf32)
    const float qscale = 0.08838834764831845f * 1.4426950408889634f;
#pragma unroll
    for (int i = 0; i < 16; i++) {
        int idx = i * 256 + tid;
        int r = idx >> 5;
        int c = (idx & 31) * 4;
        float4 v = *(const float4*)(qkv + baseQ + (size_t)(q0 + r) * QKVD + c);
        *(uint4*)&Qs[r * QST + c] = make_uint4(
            f2tf32(v.x * qscale), f2tf32(v.y * qscale),
            f2tf32(v.z * qscale), f2tf32(v.w * qscale));
    }

    float acc[16][4];
#pragma unroll
    for (int nt = 0; nt < 16; nt++)
#pragma unroll
        for (int c = 0; c < 4; c++) acc[nt][c] = 0.0f;
    float m_r0 = -1e30f, m_r1 = -1e30f;
    float l_r0 = 0.0f, l_r1 = 0.0f;

    const int vk = tid & 63;          // token within k-tile
    const int vcg_base = tid >> 6;    // 0..3

    for (int kt0 = 0; kt0 < CT; kt0 += FKT) {
        __syncthreads();

        // Load K tile (already tf32-rounded; raw bit copy)
#pragma unroll
        for (int i = 0; i < 8; i++) {
            int idx = i * 256 + tid;
            int r = idx >> 5;
            int c = (idx & 31) * 4;
            *(uint4*)&Ks[r * QST + c] =
                *(const uint4*)(qkv + baseK + (size_t)(kt0 + r) * QKVD + c);
        }
        // Load V tile TRANSPOSED: Vt[d][k] (raw bit copy)
#pragma unroll
        for (int i = 0; i < 8; i++) {
            int cg = vcg_base + i * 4;    // 0..31
            uint4 vv = *(const uint4*)(qkv + baseV
                                       + (size_t)(kt0 + vk) * QKVD + cg * 4);
            Vt[(cg * 4 + 0) * VTST + vk] = vv.x;
            Vt[(cg * 4 + 1) * VTST + vk] = vv.y;
            Vt[(cg * 4 + 2) * VTST + vk] = vv.z;
            Vt[(cg * 4 + 3) * VTST + vk] = vv.w;
        }
        if (tid < FKT)
            bias[tid] = mask[b * CT + kt0 + tid] ? 0.0f : -1e30f;
        __syncthreads();

        // ---- S = Q @ K^T (16 x 64 per warp) ----
        float s[8][4];
#pragma unroll
        for (int nt = 0; nt < 8; nt++)
#pragma unroll
            for (int c = 0; c < 4; c++) s[nt][c] = 0.0f;

#pragma unroll
        for (int ks = 0; ks < 16; ks++) {
            const uint32_t kkB = (uint32_t)(ks * 8 * 4);
            uint32_t a0, a1, a2, a3;
            ldsm_x4(a0, a1, a2, a3, aQ + kkB);
#pragma unroll
            for (int ntp = 0; ntp < 4; ntp++) {
                uint32_t b0, b1, b2, b3;
                ldsm_x4(b0, b1, b2, b3,
                        bK + (uint32_t)(ntp * 16 * QST * 4) + kkB);
                mma_tf32(s[2 * ntp][0], s[2 * ntp][1],
                         s[2 * ntp][2], s[2 * ntp][3],
                         a0, a1, a2, a3, b0, b1);
                mma_tf32(s[2 * ntp + 1][0], s[2 * ntp + 1][1],
                         s[2 * ntp + 1][2], s[2 * ntp + 1][3],
                         a0, a1, a2, a3, b2, b3);
            }
        }

        // mask bias
#pragma unroll
        for (int nt = 0; nt < 8; nt++) {
            float2 bb = *(const float2*)&bias[nt * 8 + 2 * q];
            s[nt][0] += bb.x; s[nt][1] += bb.y;
            s[nt][2] += bb.x; s[nt][3] += bb.y;
        }

        // row maxes
        float tm0 = -1e30f, tm1 = -1e30f;
#pragma unroll
        for (int nt = 0; nt < 8; nt++) {
            tm0 = fmaxf(tm0, fmaxf(s[nt][0], s[nt][1]));
            tm1 = fmaxf(tm1, fmaxf(s[nt][2], s[nt][3]));
        }
        tm0 = fmaxf(tm0, __shfl_xor_sync(0xffffffffu, tm0, 1));
        tm0 = fmaxf(tm0, __shfl_xor_sync(0xffffffffu, tm0, 2));
        tm1 = fmaxf(tm1, __shfl_xor_sync(0xffffffffu, tm1, 1));
        tm1 = fmaxf(tm1, __shfl_xor_sync(0xffffffffu, tm1, 2));

        const float mn0 = fmaxf(m_r0, tm0);
        const float mn1 = fmaxf(m_r1, tm1);
        const float corr0 = ex2(m_r0 - mn0);
        const float corr1 = ex2(m_r1 - mn1);
        m_r0 = mn0; m_r1 = mn1;

        float ps0 = 0.0f, ps1 = 0.0f;
#pragma unroll
        for (int nt = 0; nt < 8; nt++) {
            float p0 = ex2(s[nt][0] - mn0);
            float p1 = ex2(s[nt][1] - mn0);
            float p2 = ex2(s[nt][2] - mn1);
            float p3 = ex2(s[nt][3] - mn1);
            ps0 += p0 + p1;
            ps1 += p2 + p3;
            *(uint2*)&Ps[(m0 + g) * PST + nt * 8 + 2 * q] =
                make_uint2(f2tf32(p0), f2tf32(p1));
            *(uint2*)&Ps[(m0 + g + 8) * PST + nt * 8 + 2 * q] =
                make_uint2(f2tf32(p2), f2tf32(p3));
        }
        ps0 += __shfl_xor_sync(0xffffffffu, ps0, 1);
        ps0 += __shfl_xor_sync(0xffffffffu, ps0, 2);
        ps1 += __shfl_xor_sync(0xffffffffu, ps1, 1);
        ps1 += __shfl_xor_sync(0xffffffffu, ps1, 2);
        l_r0 = l_r0 * corr0 + ps0;
        l_r1 = l_r1 * corr1 + ps1;

#pragma unroll
        for (int nt = 0; nt < 16; nt++) {
            acc[nt][0] *= corr0; acc[nt][1] *= corr0;
            acc[nt][2] *= corr1; acc[nt][3] *= corr1;
        }
        __syncwarp();

        // ---- O += P @ V (16 x 128 per warp) ----
#pragma unroll
        for (int ks = 0; ks < 8; ks++) {
            const uint32_t kkB = (uint32_t)(ks * 8 * 4);
            uint32_t a0, a1, a2, a3;
            ldsm_x4(a0, a1, a2, a3, aP + kkB);
#pragma unroll
            for (int ntp = 0; ntp < 8; ntp++) {
                uint32_t b0, b1, b2, b3;
                ldsm_x4(b0, b1, b2, b3,
                        bV + (uint32_t)(ntp * 16 * VTST * 4) + kkB);
                mma_tf32(acc[2 * ntp][0], acc[2 * ntp][1],
                         acc[2 * ntp][2], acc[2 * ntp][3],
                         a0, a1, a2, a3, b0, b1);
                mma_tf32(acc[2 * ntp + 1][0], acc[2 * ntp + 1][1],
                         acc[2 * ntp + 1][2], acc[2 * ntp + 1][3],
                         a0, a1, a2, a3, b2, b3);
            }
        }
    }

    // Normalize and write y (tf32-rounded: y feeds the O-proj GEMM)
    const float inv0 = 1.0f / l_r0;
    const float inv1 = 1.0f / l_r1;
    const int row0 = q0 + m0 + g;
    const int row1 = row0 + 8;
    float* y0 = y + (size_t)(b * CT + row0) * CD + h * CHD;
    float* y1 = y + (size_t)(b * CT + row1) * CD + h * CHD;
#pragma unroll
    for (int nt = 0; nt < 16; nt++) {
        const int col = nt * 8 + 2 * q;
        *(float2*)(y0 + col) =
            make_float2(rtf(acc[nt][0] * inv0), rtf(acc[nt][1] * inv0));
        *(float2*)(y1 + col) =
            make_float2(rtf(acc[nt][2] * inv1), rtf(acc[nt][3] * inv1));
    }
}

// ---------------------------------------------------------------------------
extern "C" void kernel_launch(void* const* d_in, const int* in_sizes, int n_in,
                              void* d_out, int out_size)
{
    const float* x      = (const float*)d_in[0];
    const int*   mask   = (const int*)d_in[1];
    const float* w_qkv  = (const float*)d_in[2];
    const float* w_o    = (const float*)d_in[3];
    float*       out    = (float*)d_out;

    float *qkv = nullptr, *y = nullptr, *xt = nullptr, *wqkvt = nullptr, *wot = nullptr;
    cudaGetSymbolAddress((void**)&qkv, g_qkv);
    cudaGetSymbolAddress((void**)&y, g_y);
    cudaGetSymbolAddress((void**)&xt, g_xt);
    cudaGetSymbolAddress((void**)&wqkvt, g_wqkvt);
    cudaGetSymbolAddress((void**)&wot, g_wot);

    cudaFuncSetAttribute(sgemm_tc,
                         cudaFuncAttributeMaxDynamicSharedMemorySize,
                         SGEMM_SMEM_BYTES);
    cudaFuncSetAttribute(flash_attn_tc,
                         cudaFuncAttributeMaxDynamicSharedMemorySize,
                         FLASH_SMEM_BYTES);

    // 0) Pre-round inputs to tf32 in gmem
    {
        int n4x = (CB * CT * CD) / 4;        // 4,194,304
        int n4w = (QKVD * CD) / 4;           // 3,145,728
        int n4o = (CD * CD) / 4;             // 1,048,576
        round_tf32_kernel<<<(n4x + 255) / 256, 256>>>((const float4*)x, (float4*)xt, n4x);
        round_tf32_kernel<<<(n4w + 255) / 256, 256>>>((const float4*)w_qkv, (float4*)wqkvt, n4w);
        round_tf32_kernel<<<(n4o + 255) / 256, 256>>>((const float4*)w_o, (float4*)wot, n4o);
    }

    // 1) qkv = xt @ wqkvt^T : M=8192, N=6144, K=2048 (epilogue rounds to tf32)
    {
        dim3 grid(QKVD / 256, (CB * CT) / 128);
        sgemm_tc<<<grid, 256, SGEMM_SMEM_BYTES>>>(xt, wqkvt, qkv, CB * CT, QKVD, CD, 1);
    }

    // 2) fused attention -> y (tf32-rounded)
    {
        dim3 grid(CT / FQ, CB * CH);
        flash_attn_tc<<<grid, 256, FLASH_SMEM_BYTES>>>(qkv, mask, y);
    }

    // 3) out = y @ wot^T : M=8192, N=2048, K=2048 (full fp32 output)
    {
        dim3 grid(CD / 256, (CB * CT) / 128);
        sgemm_tc<<<grid, 256, SGEMM_SMEM_BYTES>>>(y, wot, out, CB * CT, CD, CD, 0);
    }
}

// round 13
// speedup vs baseline: 2.0871x; 2.0871x over previous
#include <cuda_runtime.h>
#include <cuda_fp16.h>
#include <cstdint>

// Problem constants
#define CB 4
#define CT 2048
#define CD 2048
#define CH 16
#define CHD 128
#define QKVD (3 * CD)   // 6144

// Scratch (allocation-free rule: __device__ globals)
__device__ __half g_qkv[(size_t)CB * CT * QKVD];   // fp16 qkv
__device__ __half g_y[(size_t)CB * CT * CD];       // fp16 attention output
__device__ __half g_xh[(size_t)CB * CT * CD];      // x in fp16
__device__ __half g_wqkvh[(size_t)QKVD * CD];      // w_qkv in fp16
__device__ __half g_woh[(size_t)CD * CD];          // w_o in fp16

__device__ __forceinline__ float ex2(float x) {
    float r;
    asm("ex2.approx.f32 %0, %1;" : "=f"(r) : "f"(x));
    return r;
}

__device__ __forceinline__ void mma_f16(
    float& c0, float& c1, float& c2, float& c3,
    uint32_t a0, uint32_t a1, uint32_t a2, uint32_t a3,
    uint32_t b0, uint32_t b1)
{
    asm volatile(
        "mma.sync.aligned.m16n8k16.row.col.f32.f16.f16.f32 "
        "{%0,%1,%2,%3}, {%4,%5,%6,%7}, {%8,%9}, {%0,%1,%2,%3};"
        : "+f"(c0), "+f"(c1), "+f"(c2), "+f"(c3)
        : "r"(a0), "r"(a1), "r"(a2), "r"(a3), "r"(b0), "r"(b1));
}

__device__ __forceinline__ void ldsm_x4(
    uint32_t& r0, uint32_t& r1, uint32_t& r2, uint32_t& r3, uint32_t addr)
{
    asm volatile(
        "ldmatrix.sync.aligned.m8n8.x4.shared.b16 {%0,%1,%2,%3}, [%4];"
        : "=r"(r0), "=r"(r1), "=r"(r2), "=r"(r3) : "r"(addr));
}
__device__ __forceinline__ void ldsm_x4_trans(
    uint32_t& r0, uint32_t& r1, uint32_t& r2, uint32_t& r3, uint32_t addr)
{
    asm volatile(
        "ldmatrix.sync.aligned.m8n8.x4.trans.shared.b16 {%0,%1,%2,%3}, [%4];"
        : "=r"(r0), "=r"(r1), "=r"(r2), "=r"(r3) : "r"(addr));
}

__device__ __forceinline__ void cp16(uint32_t smem, const void* gmem) {
    asm volatile("cp.async.cg.shared.global [%0], [%1], 16;"
                 :: "r"(smem), "l"(gmem));
}
__device__ __forceinline__ void cp_commit() {
    asm volatile("cp.async.commit_group;");
}
template <int N>
__device__ __forceinline__ void cp_wait() {
    asm volatile("cp.async.wait_group %0;" :: "n"(N));
}

// Byte offsets for b16 ldmatrix lanes. Strides in HALVES.
// A-style (m16 x k16 tile): rows m..m+15 split at +8, k split at +8 halves.
__device__ __forceinline__ uint32_t a_off16(int l, int sh) {
    return (uint32_t)((((l & 7) + ((l >> 3) & 1) * 8) * sh + (l >> 4) * 8) * 2);
}
// B-style (2 n8-tiles x k16): rows n..n+15 split at +8 (bit4), k split (bit3).
__device__ __forceinline__ uint32_t b_off16(int l, int sh) {
    return (uint32_t)(((((l >> 4) & 1) * 8 + (l & 7)) * sh + ((l >> 3) & 1) * 8) * 2);
}

// ---------------------------------------------------------------------------
// Elementwise fp32 -> fp16 conversion (round-to-nearest-even)
// ---------------------------------------------------------------------------
__global__ __launch_bounds__(256) void f32_to_f16_kernel(
    const float4* __restrict__ in, __half2* __restrict__ out, int n4)
{
    int i = blockIdx.x * blockDim.x + threadIdx.x;
    if (i < n4) {
        float4 v = in[i];
        out[2 * i]     = __floats2half2_rn(v.x, v.y);
        out[2 * i + 1] = __floats2half2_rn(v.z, v.w);
    }
}

// ===========================================================================
// fp16 tensor-core NT GEMM: C[M,N] = A[M,K] @ B[N,K]^T, A/B fp16 in gmem.
// CTA tile 128x256, BK=32, 256 threads = 8 warps (2m x 4n), warp tile 64x64.
// 4-stage cp.async ring, ONE __syncthreads per stage, ldmatrix fragments.
// outHalf: 1 -> write fp16 to Ch; 0 -> write fp32 to Cf.
// ===========================================================================
#define SAST 40                      // halves per smem row (32 + 8 pad)
#define A_BUF_H (128 * SAST)         // 5120 halves
#define B_BUF_H (256 * SAST)         // 10240 halves
#define GNST 4
#define SGEMM_SMEM_BYTES ((GNST * (A_BUF_H + B_BUF_H)) * 2)   // 122880

__global__ __launch_bounds__(256, 1) void hgemm_tc(
    const __half* __restrict__ A, const __half* __restrict__ Bm,
    float* __restrict__ Cf, __half* __restrict__ Ch,
    int M, int N, int K, int outHalf)
{
    extern __shared__ __half smh[];
    const uint32_t aSm = (uint32_t)__cvta_generic_to_shared(smh);
    const uint32_t bSm = aSm + (uint32_t)(GNST * A_BUF_H * 2);

    const int tid = threadIdx.x;
    const int wid = tid >> 5;
    const int lane = tid & 31;
    const int g = lane >> 2;
    const int q = lane & 3;

    const int warp_m = wid & 1;
    const int warp_n = wid >> 1;

    const int rowBase = blockIdx.y * 128;
    const int colBase = blockIdx.x * 256;

    // cp.async mapping: chunk = 16B = 8 halves; row = idx>>2, c = idx&3
    const int crow = tid >> 2;            // 0..63
    const int cc = (tid & 3) * 8;         // halves 0,8,16,24
    const __half* Asrc = A + (size_t)(rowBase + crow) * K + cc;
    const __half* Bsrc = Bm + (size_t)(colBase + crow) * K + cc;
    const uint32_t aDst = (uint32_t)((crow * SAST + cc) * 2);
    const uint32_t bDst = aDst;

    const uint32_t aFrag0 = aSm + a_off16(lane, SAST)
                          + (uint32_t)(warp_m * 64 * SAST * 2);
    const uint32_t bFrag0 = bSm + b_off16(lane, SAST)
                          + (uint32_t)(warp_n * 64 * SAST * 2);

    float acc[4][8][4];
#pragma unroll
    for (int mt = 0; mt < 4; mt++)
#pragma unroll
        for (int nt = 0; nt < 8; nt++)
#pragma unroll
            for (int c = 0; c < 4; c++) acc[mt][nt][c] = 0.0f;

    const int nstages = K >> 5;   // 64

    auto issue = [&](int st) {
        const int koff = st << 5;
        const int buf = st & (GNST - 1);
        const uint32_t aB = aSm + (uint32_t)(buf * A_BUF_H * 2) + aDst;
        const uint32_t bB = bSm + (uint32_t)(buf * B_BUF_H * 2) + bDst;
#pragma unroll
        for (int p = 0; p < 2; p++)
            cp16(aB + (uint32_t)(p * 64 * SAST * 2),
                 Asrc + (size_t)(p * 64) * K + koff);
#pragma unroll
        for (int p = 0; p < 4; p++)
            cp16(bB + (uint32_t)(p * 64 * SAST * 2),
                 Bsrc + (size_t)(p * 64) * K + koff);
        cp_commit();
    };

    issue(0); issue(1); issue(2);

    for (int s = 0; s < nstages; s++) {
        if (s <= nstages - 3)      cp_wait<2>();
        else if (s == nstages - 2) cp_wait<1>();
        else                       cp_wait<0>();
        __syncthreads();
        // Refill buffer (s+3)&3 == (s-1)&3: its consumer (stage s-1) finished
        // before every thread passed the sync above.
        if (s + 3 < nstages) issue(s + 3);

        const int buf = s & (GNST - 1);
        const uint32_t aOff = (uint32_t)(buf * A_BUF_H * 2);
        const uint32_t bOff = (uint32_t)(buf * B_BUF_H * 2);

#pragma unroll
        for (int kk = 0; kk < 32; kk += 16) {
            uint32_t afr[4][4];
#pragma unroll
            for (int mt = 0; mt < 4; mt++)
                ldsm_x4(afr[mt][0], afr[mt][1], afr[mt][2], afr[mt][3],
                        aFrag0 + aOff + (uint32_t)((mt * 16 * SAST + kk) * 2));
#pragma unroll
            for (int ntp = 0; ntp < 4; ntp++) {
                uint32_t b0, b1, b2, b3;
                ldsm_x4(b0, b1, b2, b3,
                        bFrag0 + bOff + (uint32_t)((ntp * 16 * SAST + kk) * 2));
#pragma unroll
                for (int mt = 0; mt < 4; mt++) {
                    mma_f16(acc[mt][2 * ntp][0], acc[mt][2 * ntp][1],
                            acc[mt][2 * ntp][2], acc[mt][2 * ntp][3],
                            afr[mt][0], afr[mt][1], afr[mt][2], afr[mt][3],
                            b0, b1);
                    mma_f16(acc[mt][2 * ntp + 1][0], acc[mt][2 * ntp + 1][1],
                            acc[mt][2 * ntp + 1][2], acc[mt][2 * ntp + 1][3],
                            afr[mt][0], afr[mt][1], afr[mt][2], afr[mt][3],
                            b2, b3);
                }
            }
        }
    }

    // Epilogue
#pragma unroll
    for (int mt = 0; mt < 4; mt++) {
        const int m0 = rowBase + warp_m * 64 + mt * 16;
#pragma unroll
        for (int nt = 0; nt < 8; nt++) {
            const int n0 = colBase + warp_n * 64 + nt * 8;
            if (outHalf) {
                *(__half2*)(Ch + (size_t)(m0 + g) * N + n0 + 2 * q) =
                    __floats2half2_rn(acc[mt][nt][0], acc[mt][nt][1]);
                *(__half2*)(Ch + (size_t)(m0 + g + 8) * N + n0 + 2 * q) =
                    __floats2half2_rn(acc[mt][nt][2], acc[mt][nt][3]);
            } else {
                *(float2*)(Cf + (size_t)(m0 + g) * N + n0 + 2 * q) =
                    make_float2(acc[mt][nt][0], acc[mt][nt][1]);
                *(float2*)(Cf + (size_t)(m0 + g + 8) * N + n0 + 2 * q) =
                    make_float2(acc[mt][nt][2], acc[mt][nt][3]);
            }
        }
    }
}

// ===========================================================================
// fp16 tensor-core flash attention (online softmax, exp2 domain).
// 256 threads = 8 warps; Q-tile 128, K-tile 64; warp owns 16 query rows.
// Q/K/V staged via cp.async (K/V double-buffered, one tile prefetch ahead).
// V used via ldmatrix.trans (no manual transpose). Softmax scale folded into
// the S rescale FMA. P through warp-private smem. y written fp16.
// ===========================================================================
#define FQ 128
#define FKT 64
#define QSTH 136   // Q/K/V smem stride in halves (272B: ldmatrix banks 4r ✓)
#define PSTH 72    // P stride (144B: banks 4r ✓)
#define KVBUF (FKT * QSTH)   // halves per K or V buffer

#define FLASH_SMEM_BYTES ((FQ * QSTH + 4 * KVBUF + FQ * PSTH) * 2 + 2 * FKT * 4)

__global__ __launch_bounds__(256, 1) void flash_attn_f16(
    const __half* __restrict__ qkv, const int* __restrict__ mask,
    __half* __restrict__ y)
{
    extern __shared__ __half smh[];
    __half* Qs = smh;                          // FQ x QSTH
    __half* Ks = Qs + FQ * QSTH;               // 2 x KVBUF
    __half* Vs = Ks + 2 * KVBUF;               // 2 x KVBUF
    __half* Ps = Vs + 2 * KVBUF;               // FQ x PSTH
    float* bias = (float*)(Ps + FQ * PSTH);    // [2][FKT]

    const int qt = blockIdx.x;
    const int bh = blockIdx.y;
    const int b = bh / CH;
    const int h = bh % CH;

    const int tid = threadIdx.x;
    const int wid = tid >> 5;
    const int lane = tid & 31;
    const int g = lane >> 2;
    const int q = lane & 3;
    const int m0 = wid * 16;

    const size_t baseQ = (size_t)b * CT * QKVD + (size_t)h * CHD;
    const size_t baseK = baseQ + CD;
    const size_t baseV = baseQ + 2 * CD;
    const int q0 = qt * FQ;

    const uint32_t qSm = (uint32_t)__cvta_generic_to_shared(Qs);
    const uint32_t kSm = (uint32_t)__cvta_generic_to_shared(Ks);
    const uint32_t vSm = (uint32_t)__cvta_generic_to_shared(Vs);
    const uint32_t pSm = (uint32_t)__cvta_generic_to_shared(Ps);

    const uint32_t aQ = qSm + a_off16(lane, QSTH) + (uint32_t)(m0 * QSTH * 2);
    const uint32_t bK = kSm + b_off16(lane, QSTH);
    const uint32_t aP = pSm + a_off16(lane, PSTH) + (uint32_t)(m0 * PSTH * 2);
    const uint32_t tV = vSm + a_off16(lane, QSTH);   // trans-ldsm lane pattern

    // cp mapping for 128-half rows: chunk = idx>>4 row, (idx&15)*8 halves
    const int krow = tid >> 4;            // 0..15
    const int kc = (tid & 15) * 8;        // halves

    // Q tile: 128 rows -> 8 passes of 16 rows
    {
#pragma unroll
        for (int p = 0; p < 8; p++) {
            int r = krow + p * 16;
            cp16(qSm + (uint32_t)((r * QSTH + kc) * 2),
                 qkv + baseQ + (size_t)(q0 + r) * QKVD + kc);
        }
        cp_commit();
    }

    auto issueKV = [&](int ti) {
        const int kt0 = ti * FKT;
        const int buf = ti & 1;
        const uint32_t kB = kSm + (uint32_t)(buf * KVBUF * 2);
        const uint32_t vB = vSm + (uint32_t)(buf * KVBUF * 2);
#pragma unroll
        for (int p = 0; p < 4; p++) {
            int r = krow + p * 16;
            cp16(kB + (uint32_t)((r * QSTH + kc) * 2),
                 qkv + baseK + (size_t)(kt0 + r) * QKVD + kc);
            cp16(vB + (uint32_t)((r * QSTH + kc) * 2),
                 qkv + baseV + (size_t)(kt0 + r) * QKVD + kc);
        }
        if (tid < FKT)
            bias[buf * FKT + tid] = mask[b * CT + kt0 + tid] ? 0.0f : -1e30f;
        cp_commit();
    };

    issueKV(0);

    float acc[16][4];
#pragma unroll
    for (int nt = 0; nt < 16; nt++)
#pragma unroll
        for (int c = 0; c < 4; c++) acc[nt][c] = 0.0f;
    float m_r0 = -1e30f, m_r1 = -1e30f;
    float l_r0 = 0.0f, l_r1 = 0.0f;

    const float cs = 0.08838834764831845f * 1.4426950408889634f; // scale*log2e
    const int ntiles = CT / FKT;

    for (int ti = 0; ti < ntiles; ti++) {
        cp_wait<0>();
        __syncthreads();
        // Prefetch next tile into the other buffer: its previous consumer
        // (tile ti-1) finished before every thread passed the sync above.
        if (ti + 1 < ntiles) issueKV(ti + 1);

        const int buf = ti & 1;
        const uint32_t kOff = (uint32_t)(buf * KVBUF * 2);
        const float* bb = bias + buf * FKT;

        // ---- S = Q @ K^T (16 x 64 per warp) ----
        float s[8][4];
#pragma unroll
        for (int nt = 0; nt < 8; nt++)
#pragma unroll
            for (int c = 0; c < 4; c++) s[nt][c] = 0.0f;

#pragma unroll
        for (int ks = 0; ks < 8; ks++) {
            const uint32_t kkB = (uint32_t)(ks * 16 * 2);
            uint32_t a0, a1, a2, a3;
            ldsm_x4(a0, a1, a2, a3, aQ + kkB);
#pragma unroll
            for (int ntp = 0; ntp < 4; ntp++) {
                uint32_t b0, b1, b2, b3;
                ldsm_x4(b0, b1, b2, b3,
                        bK + kOff + (uint32_t)(ntp * 16 * QSTH * 2) + kkB);
                mma_f16(s[2 * ntp][0], s[2 * ntp][1],
                        s[2 * ntp][2], s[2 * ntp][3],
                        a0, a1, a2, a3, b0, b1);
                mma_f16(s[2 * ntp + 1][0], s[2 * ntp + 1][1],
                        s[2 * ntp + 1][2], s[2 * ntp + 1][3],
                        a0, a1, a2, a3, b2, b3);
            }
        }

        // scale into exp2 domain + mask bias
#pragma unroll
        for (int nt = 0; nt < 8; nt++) {
            float2 bv = *(const float2*)&bb[nt * 8 + 2 * q];
            s[nt][0] = fmaf(s[nt][0], cs, bv.x);
            s[nt][1] = fmaf(s[nt][1], cs, bv.y);
            s[nt][2] = fmaf(s[nt][2], cs, bv.x);
            s[nt][3] = fmaf(s[nt][3], cs, bv.y);
        }

        // row maxes (rows g and g+8) over q lanes
        float tm0 = -1e30f, tm1 = -1e30f;
#pragma unroll
        for (int nt = 0; nt < 8; nt++) {
            tm0 = fmaxf(tm0, fmaxf(s[nt][0], s[nt][1]));
            tm1 = fmaxf(tm1, fmaxf(s[nt][2], s[nt][3]));
        }
        tm0 = fmaxf(tm0, __shfl_xor_sync(0xffffffffu, tm0, 1));
        tm0 = fmaxf(tm0, __shfl_xor_sync(0xffffffffu, tm0, 2));
        tm1 = fmaxf(tm1, __shfl_xor_sync(0xffffffffu, tm1, 1));
        tm1 = fmaxf(tm1, __shfl_xor_sync(0xffffffffu, tm1, 2));

        const float mn0 = fmaxf(m_r0, tm0);
        const float mn1 = fmaxf(m_r1, tm1);
        const float corr0 = ex2(m_r0 - mn0);
        const float corr1 = ex2(m_r1 - mn1);
        m_r0 = mn0; m_r1 = mn1;

        float ps0 = 0.0f, ps1 = 0.0f;
#pragma unroll
        for (int nt = 0; nt < 8; nt++) {
            float p0 = ex2(s[nt][0] - mn0);
            float p1 = ex2(s[nt][1] - mn0);
            float p2 = ex2(s[nt][2] - mn1);
            float p3 = ex2(s[nt][3] - mn1);
            ps0 += p0 + p1;
            ps1 += p2 + p3;
            *(__half2*)&Ps[(m0 + g) * PSTH + nt * 8 + 2 * q] =
                __floats2half2_rn(p0, p1);
            *(__half2*)&Ps[(m0 + g + 8) * PSTH + nt * 8 + 2 * q] =
                __floats2half2_rn(p2, p3);
        }
        ps0 += __shfl_xor_sync(0xffffffffu, ps0, 1);
        ps0 += __shfl_xor_sync(0xffffffffu, ps0, 2);
        ps1 += __shfl_xor_sync(0xffffffffu, ps1, 1);
        ps1 += __shfl_xor_sync(0xffffffffu, ps1, 2);
        l_r0 = l_r0 * corr0 + ps0;
        l_r1 = l_r1 * corr1 + ps1;

#pragma unroll
        for (int nt = 0; nt < 16; nt++) {
            acc[nt][0] *= corr0; acc[nt][1] *= corr0;
            acc[nt][2] *= corr1; acc[nt][3] *= corr1;
        }
        __syncwarp();   // P store -> P ldmatrix (warp-private rows)

        // ---- O += P @ V (16 x 128 per warp); V via ldmatrix.trans ----
#pragma unroll
        for (int ks = 0; ks < 4; ks++) {
            uint32_t a0, a1, a2, a3;
            ldsm_x4(a0, a1, a2, a3, aP + (uint32_t)(ks * 16 * 2));
#pragma unroll
            for (int ntp = 0; ntp < 8; ntp++) {
                uint32_t b0, b1, b2, b3;
                ldsm_x4_trans(b0, b1, b2, b3,
                              tV + kOff
                              + (uint32_t)((ks * 16 * QSTH + ntp * 16) * 2));
                mma_f16(acc[2 * ntp][0], acc[2 * ntp][1],
                        acc[2 * ntp][2], acc[2 * ntp][3],
                        a0, a1, a2, a3, b0, b1);
                mma_f16(acc[2 * ntp + 1][0], acc[2 * ntp + 1][1],
                        acc[2 * ntp + 1][2], acc[2 * ntp + 1][3],
                        a0, a1, a2, a3, b2, b3);
            }
        }
    }

    // Normalize and write y (fp16)
    const float inv0 = 1.0f / l_r0;
    const float inv1 = 1.0f / l_r1;
    const int row0 = q0 + m0 + g;
    const int row1 = row0 + 8;
    __half* y0 = y + (size_t)(b * CT + row0) * CD + h * CHD;
    __half* y1 = y + (size_t)(b * CT + row1) * CD + h * CHD;
#pragma unroll
    for (int nt = 0; nt < 16; nt++) {
        const int col = nt * 8 + 2 * q;
        *(__half2*)(y0 + col) =
            __floats2half2_rn(acc[nt][0] * inv0, acc[nt][1] * inv0);
        *(__half2*)(y1 + col) =
            __floats2half2_rn(acc[nt][2] * inv1, acc[nt][3] * inv1);
    }
}

// ---------------------------------------------------------------------------
extern "C" void kernel_launch(void* const* d_in, const int* in_sizes, int n_in,
                              void* d_out, int out_size)
{
    const float* x      = (const float*)d_in[0];
    const int*   mask   = (const int*)d_in[1];
    const float* w_qkv  = (const float*)d_in[2];
    const float* w_o    = (const float*)d_in[3];
    float*       out    = (float*)d_out;

    __half *qkv = nullptr, *y = nullptr, *xh = nullptr, *wqkvh = nullptr, *woh = nullptr;
    cudaGetSymbolAddress((void**)&qkv, g_qkv);
    cudaGetSymbolAddress((void**)&y, g_y);
    cudaGetSymbolAddress((void**)&xh, g_xh);
    cudaGetSymbolAddress((void**)&wqkvh, g_wqkvh);
    cudaGetSymbolAddress((void**)&woh, g_woh);

    cudaFuncSetAttribute(hgemm_tc,
                         cudaFuncAttributeMaxDynamicSharedMemorySize,
                         SGEMM_SMEM_BYTES);
    cudaFuncSetAttribute(flash_attn_f16,
                         cudaFuncAttributeMaxDynamicSharedMemorySize,
                         FLASH_SMEM_BYTES);

    // 0) Convert inputs to fp16
    {
        int n4x = (CB * CT * CD) / 4;
        int n4w = (QKVD * CD) / 4;
        int n4o = (CD * CD) / 4;
        f32_to_f16_kernel<<<(n4x + 255) / 256, 256>>>((const float4*)x, (__half2*)xh, n4x);
        f32_to_f16_kernel<<<(n4w + 255) / 256, 256>>>((const float4*)w_qkv, (__half2*)wqkvh, n4w);
        f32_to_f16_kernel<<<(n4o + 255) / 256, 256>>>((const float4*)w_o, (__half2*)woh, n4o);
    }

    // 1) qkv = xh @ wqkvh^T : M=8192, N=6144, K=2048 (fp16 out)
    {
        dim3 grid(QKVD / 256, (CB * CT) / 128);
        hgemm_tc<<<grid, 256, SGEMM_SMEM_BYTES>>>(
            xh, wqkvh, nullptr, qkv, CB * CT, QKVD, CD, 1);
    }

    // 2) fused attention -> y (fp16)
    {
        dim3 grid(CT / FQ, CB * CH);
        flash_attn_f16<<<grid, 256, FLASH_SMEM_BYTES>>>(qkv, mask, y);
    }

    // 3) out = y @ woh^T : M=8192, N=2048, K=2048 (fp32 out)
    {
        dim3 grid(CD / 256, (CB * CT) / 128);
        hgemm_tc<<<grid, 256, SGEMM_SMEM_BYTES>>>(
            y, woh, out, nullptr, CB * CT, CD, CD, 0);
    }
}

// round 14
// speedup vs baseline: 2.2922x; 1.0983x over previous
#include <cuda_runtime.h>
#include <cuda_fp16.h>
#include <cstdint>

// Problem constants
#define CB 4
#define CT 2048
#define CD 2048
#define CH 16
#define CHD 128
#define QKVD (3 * CD)   // 6144

// Scratch (allocation-free rule: __device__ globals)
__device__ __half g_qkv[(size_t)CB * CT * QKVD];   // fp16 qkv
__device__ __half g_y[(size_t)CB * CT * CD];       // fp16 attention output
__device__ __half g_xh[(size_t)CB * CT * CD];      // x in fp16
__device__ __half g_wqkvh[(size_t)QKVD * CD];      // w_qkv in fp16
__device__ __half g_woh[(size_t)CD * CD];          // w_o in fp16

__device__ __forceinline__ float ex2(float x) {
    float r;
    asm("ex2.approx.f32 %0, %1;" : "=f"(r) : "f"(x));
    return r;
}

__device__ __forceinline__ void mma_f16(
    float& c0, float& c1, float& c2, float& c3,
    uint32_t a0, uint32_t a1, uint32_t a2, uint32_t a3,
    uint32_t b0, uint32_t b1)
{
    asm volatile(
        "mma.sync.aligned.m16n8k16.row.col.f32.f16.f16.f32 "
        "{%0,%1,%2,%3}, {%4,%5,%6,%7}, {%8,%9}, {%0,%1,%2,%3};"
        : "+f"(c0), "+f"(c1), "+f"(c2), "+f"(c3)
        : "r"(a0), "r"(a1), "r"(a2), "r"(a3), "r"(b0), "r"(b1));
}

__device__ __forceinline__ void ldsm_x4(
    uint32_t& r0, uint32_t& r1, uint32_t& r2, uint32_t& r3, uint32_t addr)
{
    asm volatile(
        "ldmatrix.sync.aligned.m8n8.x4.shared.b16 {%0,%1,%2,%3}, [%4];"
        : "=r"(r0), "=r"(r1), "=r"(r2), "=r"(r3) : "r"(addr));
}
__device__ __forceinline__ void ldsm_x4_trans(
    uint32_t& r0, uint32_t& r1, uint32_t& r2, uint32_t& r3, uint32_t addr)
{
    asm volatile(
        "ldmatrix.sync.aligned.m8n8.x4.trans.shared.b16 {%0,%1,%2,%3}, [%4];"
        : "=r"(r0), "=r"(r1), "=r"(r2), "=r"(r3) : "r"(addr));
}

__device__ __forceinline__ void cp16(uint32_t smem, const void* gmem) {
    asm volatile("cp.async.cg.shared.global [%0], [%1], 16;"
                 :: "r"(smem), "l"(gmem));
}
__device__ __forceinline__ void cp_commit() {
    asm volatile("cp.async.commit_group;");
}
template <int N>
__device__ __forceinline__ void cp_wait() {
    asm volatile("cp.async.wait_group %0;" :: "n"(N));
}

// Byte offsets for b16 ldmatrix lanes. Strides in HALVES.
__device__ __forceinline__ uint32_t a_off16(int l, int sh) {
    return (uint32_t)((((l & 7) + ((l >> 3) & 1) * 8) * sh + (l >> 4) * 8) * 2);
}
__device__ __forceinline__ uint32_t b_off16(int l, int sh) {
    return (uint32_t)(((((l >> 4) & 1) * 8 + (l & 7)) * sh + ((l >> 3) & 1) * 8) * 2);
}

// ---------------------------------------------------------------------------
// Elementwise fp32 -> fp16 conversion
// ---------------------------------------------------------------------------
__global__ __launch_bounds__(256) void f32_to_f16_kernel(
    const float4* __restrict__ in, __half2* __restrict__ out, int n4)
{
    int i = blockIdx.x * blockDim.x + threadIdx.x;
    if (i < n4) {
        float4 v = in[i];
        out[2 * i]     = __floats2half2_rn(v.x, v.y);
        out[2 * i + 1] = __floats2half2_rn(v.z, v.w);
    }
}

// ===========================================================================
// fp16 tensor-core NT GEMM: C[M,N] = A[M,K] @ B[N,K]^T, A/B fp16 in gmem.
// CTA tile 128x256, BK=64, 256 threads = 8 warps (2m x 4n), warp tile 64x64.
// 3-stage cp.async ring (one sync per 64-deep k stage) + register-level
// fragment double-buffering across the four k16 sub-steps.
// ===========================================================================
#define SAST 72                      // halves per smem row (64 + 8 pad)
#define A_BUF_H (128 * SAST)         // 9216 halves
#define B_BUF_H (256 * SAST)         // 18432 halves
#define GNST 3
#define SGEMM_SMEM_BYTES ((GNST * (A_BUF_H + B_BUF_H)) * 2)   // 165888

__global__ __launch_bounds__(256, 1) void hgemm_tc(
    const __half* __restrict__ A, const __half* __restrict__ Bm,
    float* __restrict__ Cf, __half* __restrict__ Ch,
    int M, int N, int K, int outHalf)
{
    extern __shared__ __half smh[];
    const uint32_t aSm = (uint32_t)__cvta_generic_to_shared(smh);
    const uint32_t bSm = aSm + (uint32_t)(GNST * A_BUF_H * 2);

    const int tid = threadIdx.x;
    const int wid = tid >> 5;
    const int lane = tid & 31;
    const int g = lane >> 2;
    const int q = lane & 3;

    const int warp_m = wid & 1;
    const int warp_n = wid >> 1;

    const int rowBase = blockIdx.y * 128;
    const int colBase = blockIdx.x * 256;

    // cp.async mapping: row chunk = 8 halves; 8 chunks per 64-half row.
    const int arow = tid >> 3;            // 0..31
    const int ac = (tid & 7) * 8;         // halves 0..56
    const __half* Asrc = A + (size_t)(rowBase + arow) * K + ac;
    const __half* Bsrc = Bm + (size_t)(colBase + arow) * K + ac;
    const uint32_t dDst = (uint32_t)((arow * SAST + ac) * 2);

    const uint32_t aFrag0 = aSm + a_off16(lane, SAST)
                          + (uint32_t)(warp_m * 64 * SAST * 2);
    const uint32_t bFrag0 = bSm + b_off16(lane, SAST)
                          + (uint32_t)(warp_n * 64 * SAST * 2);

    float acc[4][8][4];
#pragma unroll
    for (int mt = 0; mt < 4; mt++)
#pragma unroll
        for (int nt = 0; nt < 8; nt++)
#pragma unroll
            for (int c = 0; c < 4; c++) acc[mt][nt][c] = 0.0f;

    const int nstages = K >> 6;   // K/64 = 32

    auto issue = [&](int st) {
        const int koff = st << 6;
        const int buf = st % GNST;
        const uint32_t aB = aSm + (uint32_t)(buf * A_BUF_H * 2) + dDst;
        const uint32_t bB = bSm + (uint32_t)(buf * B_BUF_H * 2) + dDst;
#pragma unroll
        for (int p = 0; p < 4; p++)
            cp16(aB + (uint32_t)(p * 32 * SAST * 2),
                 Asrc + (size_t)(p * 32) * K + koff);
#pragma unroll
        for (int p = 0; p < 8; p++)
            cp16(bB + (uint32_t)(p * 32 * SAST * 2),
                 Bsrc + (size_t)(p * 32) * K + koff);
        cp_commit();
    };

    issue(0); issue(1);

    for (int s = 0; s < nstages; s++) {
        if (s < nstages - 1) cp_wait<1>();
        else                 cp_wait<0>();
        __syncthreads();
        // Refill buffer (s+2)%3 == (s-1)%3: stage s-1's consumers finished
        // before every thread passed the sync above.
        if (s + 2 < nstages) issue(s + 2);

        const int buf = s % GNST;
        const uint32_t aOff = (uint32_t)(buf * A_BUF_H * 2);
        const uint32_t bOff = (uint32_t)(buf * B_BUF_H * 2);

        uint32_t af[2][4][4];   // [slot][mt][reg]
        uint32_t bf[2][4][4];   // [slot][ntp][reg]

        // Prime slot 0 with k-step 0
#pragma unroll
        for (int mt = 0; mt < 4; mt++)
            ldsm_x4(af[0][mt][0], af[0][mt][1], af[0][mt][2], af[0][mt][3],
                    aFrag0 + aOff + (uint32_t)((mt * 16 * SAST) * 2));
#pragma unroll
        for (int ntp = 0; ntp < 4; ntp++)
            ldsm_x4(bf[0][ntp][0], bf[0][ntp][1], bf[0][ntp][2], bf[0][ntp][3],
                    bFrag0 + bOff + (uint32_t)((ntp * 16 * SAST) * 2));

#pragma unroll
        for (int ks = 0; ks < 4; ks++) {
            const int cur = ks & 1;
            const int nxt = cur ^ 1;
            // Prefetch k-step ks+1 while computing ks
            if (ks < 3) {
                const uint32_t kkB = (uint32_t)((ks + 1) * 16 * 2);
#pragma unroll
                for (int mt = 0; mt < 4; mt++)
                    ldsm_x4(af[nxt][mt][0], af[nxt][mt][1],
                            af[nxt][mt][2], af[nxt][mt][3],
                            aFrag0 + aOff
                            + (uint32_t)((mt * 16 * SAST) * 2) + kkB);
#pragma unroll
                for (int ntp = 0; ntp < 4; ntp++)
                    ldsm_x4(bf[nxt][ntp][0], bf[nxt][ntp][1],
                            bf[nxt][ntp][2], bf[nxt][ntp][3],
                            bFrag0 + bOff
                            + (uint32_t)((ntp * 16 * SAST) * 2) + kkB);
            }
#pragma unroll
            for (int ntp = 0; ntp < 4; ntp++) {
#pragma unroll
                for (int mt = 0; mt < 4; mt++) {
                    mma_f16(acc[mt][2 * ntp][0], acc[mt][2 * ntp][1],
                            acc[mt][2 * ntp][2], acc[mt][2 * ntp][3],
                            af[cur][mt][0], af[cur][mt][1],
                            af[cur][mt][2], af[cur][mt][3],
                            bf[cur][ntp][0], bf[cur][ntp][1]);
                    mma_f16(acc[mt][2 * ntp + 1][0], acc[mt][2 * ntp + 1][1],
                            acc[mt][2 * ntp + 1][2], acc[mt][2 * ntp + 1][3],
                            af[cur][mt][0], af[cur][mt][1],
                            af[cur][mt][2], af[cur][mt][3],
                            bf[cur][ntp][2], bf[cur][ntp][3]);
                }
            }
        }
    }

    // Epilogue
#pragma unroll
    for (int mt = 0; mt < 4; mt++) {
        const int m0 = rowBase + warp_m * 64 + mt * 16;
#pragma unroll
        for (int nt = 0; nt < 8; nt++) {
            const int n0 = colBase + warp_n * 64 + nt * 8;
            if (outHalf) {
                *(__half2*)(Ch + (size_t)(m0 + g) * N + n0 + 2 * q) =
                    __floats2half2_rn(acc[mt][nt][0], acc[mt][nt][1]);
                *(__half2*)(Ch + (size_t)(m0 + g + 8) * N + n0 + 2 * q) =
                    __floats2half2_rn(acc[mt][nt][2], acc[mt][nt][3]);
            } else {
                *(float2*)(Cf + (size_t)(m0 + g) * N + n0 + 2 * q) =
                    make_float2(acc[mt][nt][0], acc[mt][nt][1]);
                *(float2*)(Cf + (size_t)(m0 + g + 8) * N + n0 + 2 * q) =
                    make_float2(acc[mt][nt][2], acc[mt][nt][3]);
            }
        }
    }
}

// ===========================================================================
// fp16 tensor-core flash attention (unchanged from R13).
// ===========================================================================
#define FQ 128
#define FKT 64
#define QSTH 136
#define PSTH 72
#define KVBUF (FKT * QSTH)

#define FLASH_SMEM_BYTES ((FQ * QSTH + 4 * KVBUF + FQ * PSTH) * 2 + 2 * FKT * 4)

__global__ __launch_bounds__(256, 1) void flash_attn_f16(
    const __half* __restrict__ qkv, const int* __restrict__ mask,
    __half* __restrict__ y)
{
    extern __shared__ __half smh[];
    __half* Qs = smh;                          // FQ x QSTH
    __half* Ks = Qs + FQ * QSTH;               // 2 x KVBUF
    __half* Vs = Ks + 2 * KVBUF;               // 2 x KVBUF
    __half* Ps = Vs + 2 * KVBUF;               // FQ x PSTH
    float* bias = (float*)(Ps + FQ * PSTH);    // [2][FKT]

    const int qt = blockIdx.x;
    const int bh = blockIdx.y;
    const int b = bh / CH;
    const int h = bh % CH;

    const int tid = threadIdx.x;
    const int wid = tid >> 5;
    const int lane = tid & 31;
    const int g = lane >> 2;
    const int q = lane & 3;
    const int m0 = wid * 16;

    const size_t baseQ = (size_t)b * CT * QKVD + (size_t)h * CHD;
    const size_t baseK = baseQ + CD;
    const size_t baseV = baseQ + 2 * CD;
    const int q0 = qt * FQ;

    const uint32_t qSm = (uint32_t)__cvta_generic_to_shared(Qs);
    const uint32_t kSm = (uint32_t)__cvta_generic_to_shared(Ks);
    const uint32_t vSm = (uint32_t)__cvta_generic_to_shared(Vs);
    const uint32_t pSm = (uint32_t)__cvta_generic_to_shared(Ps);

    const uint32_t aQ = qSm + a_off16(lane, QSTH) + (uint32_t)(m0 * QSTH * 2);
    const uint32_t bK = kSm + b_off16(lane, QSTH);
    const uint32_t aP = pSm + a_off16(lane, PSTH) + (uint32_t)(m0 * PSTH * 2);
    const uint32_t tV = vSm + a_off16(lane, QSTH);

    const int krow = tid >> 4;            // 0..15
    const int kc = (tid & 15) * 8;        // halves

    // Q tile
    {
#pragma unroll
        for (int p = 0; p < 8; p++) {
            int r = krow + p * 16;
            cp16(qSm + (uint32_t)((r * QSTH + kc) * 2),
                 qkv + baseQ + (size_t)(q0 + r) * QKVD + kc);
        }
        cp_commit();
    }

    auto issueKV = [&](int ti) {
        const int kt0 = ti * FKT;
        const int buf = ti & 1;
        const uint32_t kB = kSm + (uint32_t)(buf * KVBUF * 2);
        const uint32_t vB = vSm + (uint32_t)(buf * KVBUF * 2);
#pragma unroll
        for (int p = 0; p < 4; p++) {
            int r = krow + p * 16;
            cp16(kB + (uint32_t)((r * QSTH + kc) * 2),
                 qkv + baseK + (size_t)(kt0 + r) * QKVD + kc);
            cp16(vB + (uint32_t)((r * QSTH + kc) * 2),
                 qkv + baseV + (size_t)(kt0 + r) * QKVD + kc);
        }
        if (tid < FKT)
            bias[buf * FKT + tid] = mask[b * CT + kt0 + tid] ? 0.0f : -1e30f;
        cp_commit();
    };

    issueKV(0);

    float acc[16][4];
#pragma unroll
    for (int nt = 0; nt < 16; nt++)
#pragma unroll
        for (int c = 0; c < 4; c++) acc[nt][c] = 0.0f;
    float m_r0 = -1e30f, m_r1 = -1e30f;
    float l_r0 = 0.0f, l_r1 = 0.0f;

    const float cs = 0.08838834764831845f * 1.4426950408889634f;
    const int ntiles = CT / FKT;

    for (int ti = 0; ti < ntiles; ti++) {
        cp_wait<0>();
        __syncthreads();
        if (ti + 1 < ntiles) issueKV(ti + 1);

        const int buf = ti & 1;
        const uint32_t kOff = (uint32_t)(buf * KVBUF * 2);
        const float* bb = bias + buf * FKT;

        // ---- S = Q @ K^T ----
        float s[8][4];
#pragma unroll
        for (int nt = 0; nt < 8; nt++)
#pragma unroll
            for (int c = 0; c < 4; c++) s[nt][c] = 0.0f;

#pragma unroll
        for (int ks = 0; ks < 8; ks++) {
            const uint32_t kkB = (uint32_t)(ks * 16 * 2);
            uint32_t a0, a1, a2, a3;
            ldsm_x4(a0, a1, a2, a3, aQ + kkB);
#pragma unroll
            for (int ntp = 0; ntp < 4; ntp++) {
                uint32_t b0, b1, b2, b3;
                ldsm_x4(b0, b1, b2, b3,
                        bK + kOff + (uint32_t)(ntp * 16 * QSTH * 2) + kkB);
                mma_f16(s[2 * ntp][0], s[2 * ntp][1],
                        s[2 * ntp][2], s[2 * ntp][3],
                        a0, a1, a2, a3, b0, b1);
                mma_f16(s[2 * ntp + 1][0], s[2 * ntp + 1][1],
                        s[2 * ntp + 1][2], s[2 * ntp + 1][3],
                        a0, a1, a2, a3, b2, b3);
            }
        }

#pragma unroll
        for (int nt = 0; nt < 8; nt++) {
            float2 bv = *(const float2*)&bb[nt * 8 + 2 * q];
            s[nt][0] = fmaf(s[nt][0], cs, bv.x);
            s[nt][1] = fmaf(s[nt][1], cs, bv.y);
            s[nt][2] = fmaf(s[nt][2], cs, bv.x);
            s[nt][3] = fmaf(s[nt][3], cs, bv.y);
        }

        float tm0 = -1e30f, tm1 = -1e30f;
#pragma unroll
        for (int nt = 0; nt < 8; nt++) {
            tm0 = fmaxf(tm0, fmaxf(s[nt][0], s[nt][1]));
            tm1 = fmaxf(tm1, fmaxf(s[nt][2], s[nt][3]));
        }
        tm0 = fmaxf(tm0, __shfl_xor_sync(0xffffffffu, tm0, 1));
        tm0 = fmaxf(tm0, __shfl_xor_sync(0xffffffffu, tm0, 2));
        tm1 = fmaxf(tm1, __shfl_xor_sync(0xffffffffu, tm1, 1));
        tm1 = fmaxf(tm1, __shfl_xor_sync(0xffffffffu, tm1, 2));

        const float mn0 = fmaxf(m_r0, tm0);
        const float mn1 = fmaxf(m_r1, tm1);
        const float corr0 = ex2(m_r0 - mn0);
        const float corr1 = ex2(m_r1 - mn1);
        m_r0 = mn0; m_r1 = mn1;

        float ps0 = 0.0f, ps1 = 0.0f;
#pragma unroll
        for (int nt = 0; nt < 8; nt++) {
            float p0 = ex2(s[nt][0] - mn0);
            float p1 = ex2(s[nt][1] - mn0);
            float p2 = ex2(s[nt][2] - mn1);
            float p3 = ex2(s[nt][3] - mn1);
            ps0 += p0 + p1;
            ps1 += p2 + p3;
            *(__half2*)&Ps[(m0 + g) * PSTH + nt * 8 + 2 * q] =
                __floats2half2_rn(p0, p1);
            *(__half2*)&Ps[(m0 + g + 8) * PSTH + nt * 8 + 2 * q] =
                __floats2half2_rn(p2, p3);
        }
        ps0 += __shfl_xor_sync(0xffffffffu, ps0, 1);
        ps0 += __shfl_xor_sync(0xffffffffu, ps0, 2);
        ps1 += __shfl_xor_sync(0xffffffffu, ps1, 1);
        ps1 += __shfl_xor_sync(0xffffffffu, ps1, 2);
        l_r0 = l_r0 * corr0 + ps0;
        l_r1 = l_r1 * corr1 + ps1;

#pragma unroll
        for (int nt = 0; nt < 16; nt++) {
            acc[nt][0] *= corr0; acc[nt][1] *= corr0;
            acc[nt][2] *= corr1; acc[nt][3] *= corr1;
        }
        __syncwarp();

        // ---- O += P @ V ----
#pragma unroll
        for (int ks = 0; ks < 4; ks++) {
            uint32_t a0, a1, a2, a3;
            ldsm_x4(a0, a1, a2, a3, aP + (uint32_t)(ks * 16 * 2));
#pragma unroll
            for (int ntp = 0; ntp < 8; ntp++) {
                uint32_t b0, b1, b2, b3;
                ldsm_x4_trans(b0, b1, b2, b3,
                              tV + kOff
                              + (uint32_t)((ks * 16 * QSTH + ntp * 16) * 2));
                mma_f16(acc[2 * ntp][0], acc[2 * ntp][1],
                        acc[2 * ntp][2], acc[2 * ntp][3],
                        a0, a1, a2, a3, b0, b1);
                mma_f16(acc[2 * ntp + 1][0], acc[2 * ntp + 1][1],
                        acc[2 * ntp + 1][2], acc[2 * ntp + 1][3],
                        a0, a1, a2, a3, b2, b3);
            }
        }
    }

    const float inv0 = 1.0f / l_r0;
    const float inv1 = 1.0f / l_r1;
    const int row0 = q0 + m0 + g;
    const int row1 = row0 + 8;
    __half* y0 = y + (size_t)(b * CT + row0) * CD + h * CHD;
    __half* y1 = y + (size_t)(b * CT + row1) * CD + h * CHD;
#pragma unroll
    for (int nt = 0; nt < 16; nt++) {
        const int col = nt * 8 + 2 * q;
        *(__half2*)(y0 + col) =
            __floats2half2_rn(acc[nt][0] * inv0, acc[nt][1] * inv0);
        *(__half2*)(y1 + col) =
            __floats2half2_rn(acc[nt][2] * inv1, acc[nt][3] * inv1);
    }
}

// ---------------------------------------------------------------------------
extern "C" void kernel_launch(void* const* d_in, const int* in_sizes, int n_in,
                              void* d_out, int out_size)
{
    const float* x      = (const float*)d_in[0];
    const int*   mask   = (const int*)d_in[1];
    const float* w_qkv  = (const float*)d_in[2];
    const float* w_o    = (const float*)d_in[3];
    float*       out    = (float*)d_out;

    __half *qkv = nullptr, *y = nullptr, *xh = nullptr, *wqkvh = nullptr, *woh = nullptr;
    cudaGetSymbolAddress((void**)&qkv, g_qkv);
    cudaGetSymbolAddress((void**)&y, g_y);
    cudaGetSymbolAddress((void**)&xh, g_xh);
    cudaGetSymbolAddress((void**)&wqkvh, g_wqkvh);
    cudaGetSymbolAddress((void**)&woh, g_woh);

    cudaFuncSetAttribute(hgemm_tc,
                         cudaFuncAttributeMaxDynamicSharedMemorySize,
                         SGEMM_SMEM_BYTES);
    cudaFuncSetAttribute(flash_attn_f16,
                         cudaFuncAttributeMaxDynamicSharedMemorySize,
                         FLASH_SMEM_BYTES);

    // 0) Convert inputs to fp16
    {
        int n4x = (CB * CT * CD) / 4;
        int n4w = (QKVD * CD) / 4;
        int n4o = (CD * CD) / 4;
        f32_to_f16_kernel<<<(n4x + 255) / 256, 256>>>((const float4*)x, (__half2*)xh, n4x);
        f32_to_f16_kernel<<<(n4w + 255) / 256, 256>>>((const float4*)w_qkv, (__half2*)wqkvh, n4w);
        f32_to_f16_kernel<<<(n4o + 255) / 256, 256>>>((const float4*)w_o, (__half2*)woh, n4o);
    }

    // 1) qkv = xh @ wqkvh^T : M=8192, N=6144, K=2048 (fp16 out)
    {
        dim3 grid(QKVD / 256, (CB * CT) / 128);
        hgemm_tc<<<grid, 256, SGEMM_SMEM_BYTES>>>(
            xh, wqkvh, nullptr, qkv, CB * CT, QKVD, CD, 1);
    }

    // 2) fused attention -> y (fp16)
    {
        dim3 grid(CT / FQ, CB * CH);
        flash_attn_f16<<<grid, 256, FLASH_SMEM_BYTES>>>(qkv, mask, y);
    }

    // 3) out = y @ woh^T : M=8192, N=2048, K=2048 (fp32 out)
    {
        dim3 grid(CD / 256, (CB * CT) / 128);
        hgemm_tc<<<grid, 256, SGEMM_SMEM_BYTES>>>(
            y, woh, out, nullptr, CB * CT, CD, CD, 0);
    }
}

// round 15
// speedup vs baseline: 2.3126x; 1.0089x over previous
#include <cuda_runtime.h>
#include <cuda_fp16.h>
#include <cstdint>

// Problem constants
#define CB 4
#define CT 2048
#define CD 2048
#define CH 16
#define CHD 128
#define QKVD (3 * CD)   // 6144

// Scratch (allocation-free rule: __device__ globals)
__device__ __half g_qkv[(size_t)CB * CT * QKVD];   // fp16 qkv
__device__ __half g_y[(size_t)CB * CT * CD];       // fp16 attention output
__device__ __half g_xh[(size_t)CB * CT * CD];      // x in fp16
__device__ __half g_wqkvh[(size_t)QKVD * CD];      // w_qkv in fp16
__device__ __half g_woh[(size_t)CD * CD];          // w_o in fp16

__device__ __forceinline__ float ex2(float x) {
    float r;
    asm("ex2.approx.f32 %0, %1;" : "=f"(r) : "f"(x));
    return r;
}

__device__ __forceinline__ void mma_f16(
    float& c0, float& c1, float& c2, float& c3,
    uint32_t a0, uint32_t a1, uint32_t a2, uint32_t a3,
    uint32_t b0, uint32_t b1)
{
    asm volatile(
        "mma.sync.aligned.m16n8k16.row.col.f32.f16.f16.f32 "
        "{%0,%1,%2,%3}, {%4,%5,%6,%7}, {%8,%9}, {%0,%1,%2,%3};"
        : "+f"(c0), "+f"(c1), "+f"(c2), "+f"(c3)
        : "r"(a0), "r"(a1), "r"(a2), "r"(a3), "r"(b0), "r"(b1));
}

__device__ __forceinline__ void ldsm_x4(
    uint32_t& r0, uint32_t& r1, uint32_t& r2, uint32_t& r3, uint32_t addr)
{
    asm volatile(
        "ldmatrix.sync.aligned.m8n8.x4.shared.b16 {%0,%1,%2,%3}, [%4];"
        : "=r"(r0), "=r"(r1), "=r"(r2), "=r"(r3) : "r"(addr));
}
__device__ __forceinline__ void ldsm_x4_trans(
    uint32_t& r0, uint32_t& r1, uint32_t& r2, uint32_t& r3, uint32_t addr)
{
    asm volatile(
        "ldmatrix.sync.aligned.m8n8.x4.trans.shared.b16 {%0,%1,%2,%3}, [%4];"
        : "=r"(r0), "=r"(r1), "=r"(r2), "=r"(r3) : "r"(addr));
}

__device__ __forceinline__ void cp16(uint32_t smem, const void* gmem) {
    asm volatile("cp.async.cg.shared.global [%0], [%1], 16;"
                 :: "r"(smem), "l"(gmem));
}
__device__ __forceinline__ void cp_commit() {
    asm volatile("cp.async.commit_group;");
}
template <int N>
__device__ __forceinline__ void cp_wait() {
    asm volatile("cp.async.wait_group %0;" :: "n"(N));
}

// Byte offsets for b16 ldmatrix lanes. Strides in HALVES.
__device__ __forceinline__ uint32_t a_off16(int l, int sh) {
    return (uint32_t)((((l & 7) + ((l >> 3) & 1) * 8) * sh + (l >> 4) * 8) * 2);
}
__device__ __forceinline__ uint32_t b_off16(int l, int sh) {
    return (uint32_t)(((((l >> 4) & 1) * 8 + (l & 7)) * sh + ((l >> 3) & 1) * 8) * 2);
}

// ---------------------------------------------------------------------------
// Elementwise fp32 -> fp16 conversion
// ---------------------------------------------------------------------------
__global__ __launch_bounds__(256) void f32_to_f16_kernel(
    const float4* __restrict__ in, __half2* __restrict__ out, int n4)
{
    int i = blockIdx.x * blockDim.x + threadIdx.x;
    if (i < n4) {
        float4 v = in[i];
        out[2 * i]     = __floats2half2_rn(v.x, v.y);
        out[2 * i + 1] = __floats2half2_rn(v.z, v.w);
    }
}

// ===========================================================================
// fp16 tensor-core NT GEMM: C[M,N] = A[M,K] @ B[N,K]^T, A/B fp16 in gmem.
// CTA tile 128x256, BK=64, 512 threads = 16 warps (2m x 8n), warp tile 64x32.
// 3-stage cp.async ring, one sync per stage, 4 warps/SMSP for latency hiding.
// ===========================================================================
#define SAST 72                      // halves per smem row (64 + 8 pad)
#define A_BUF_H (128 * SAST)         // 9216 halves
#define B_BUF_H (256 * SAST)         // 18432 halves
#define GNST 3
#define SGEMM_SMEM_BYTES ((GNST * (A_BUF_H + B_BUF_H)) * 2)   // 165888
#define GTHREADS 512

__global__ __launch_bounds__(GTHREADS, 1) void hgemm_tc(
    const __half* __restrict__ A, const __half* __restrict__ Bm,
    float* __restrict__ Cf, __half* __restrict__ Ch,
    int M, int N, int K, int outHalf)
{
    extern __shared__ __half smh[];
    const uint32_t aSm = (uint32_t)__cvta_generic_to_shared(smh);
    const uint32_t bSm = aSm + (uint32_t)(GNST * A_BUF_H * 2);

    const int tid = threadIdx.x;
    const int wid = tid >> 5;             // 0..15
    const int lane = tid & 31;
    const int g = lane >> 2;
    const int q = lane & 3;

    const int warp_m = wid & 1;           // 0..1 -> m offset *64
    const int warp_n = wid >> 1;          // 0..7 -> n offset *32

    const int rowBase = blockIdx.y * 128;
    const int colBase = blockIdx.x * 256;

    // cp.async mapping: row chunk = 8 halves; 8 chunks per 64-half row.
    const int arow = tid >> 3;            // 0..63
    const int ac = (tid & 7) * 8;         // halves 0..56
    const __half* Asrc = A + (size_t)(rowBase + arow) * K + ac;
    const __half* Bsrc = Bm + (size_t)(colBase + arow) * K + ac;
    const uint32_t dDst = (uint32_t)((arow * SAST + ac) * 2);

    const uint32_t aFrag0 = aSm + a_off16(lane, SAST)
                          + (uint32_t)(warp_m * 64 * SAST * 2);
    const uint32_t bFrag0 = bSm + b_off16(lane, SAST)
                          + (uint32_t)(warp_n * 32 * SAST * 2);

    float acc[4][4][4];   // [mt][nt][c] : warp tile 64(m) x 32(n)
#pragma unroll
    for (int mt = 0; mt < 4; mt++)
#pragma unroll
        for (int nt = 0; nt < 4; nt++)
#pragma unroll
            for (int c = 0; c < 4; c++) acc[mt][nt][c] = 0.0f;

    const int nstages = K >> 6;   // K/64 = 32

    auto issue = [&](int st) {
        const int koff = st << 6;
        const int buf = st % GNST;
        const uint32_t aB = aSm + (uint32_t)(buf * A_BUF_H * 2) + dDst;
        const uint32_t bB = bSm + (uint32_t)(buf * B_BUF_H * 2) + dDst;
#pragma unroll
        for (int p = 0; p < 2; p++)
            cp16(aB + (uint32_t)(p * 64 * SAST * 2),
                 Asrc + (size_t)(p * 64) * K + koff);
#pragma unroll
        for (int p = 0; p < 4; p++)
            cp16(bB + (uint32_t)(p * 64 * SAST * 2),
                 Bsrc + (size_t)(p * 64) * K + koff);
        cp_commit();
    };

    issue(0); issue(1);

    for (int s = 0; s < nstages; s++) {
        if (s < nstages - 1) cp_wait<1>();
        else                 cp_wait<0>();
        __syncthreads();
        // Refill buffer (s+2)%3 == (s-1)%3: stage s-1's consumers finished
        // before every thread passed the sync above.
        if (s + 2 < nstages) issue(s + 2);

        const int buf = s % GNST;
        const uint32_t aOff = (uint32_t)(buf * A_BUF_H * 2);
        const uint32_t bOff = (uint32_t)(buf * B_BUF_H * 2);

#pragma unroll
        for (int ks = 0; ks < 4; ks++) {
            const uint32_t kkB = (uint32_t)(ks * 16 * 2);
            uint32_t afr[4][4];
#pragma unroll
            for (int mt = 0; mt < 4; mt++)
                ldsm_x4(afr[mt][0], afr[mt][1], afr[mt][2], afr[mt][3],
                        aFrag0 + aOff + (uint32_t)((mt * 16 * SAST) * 2) + kkB);
#pragma unroll
            for (int ntp = 0; ntp < 2; ntp++) {
                uint32_t b0, b1, b2, b3;
                ldsm_x4(b0, b1, b2, b3,
                        bFrag0 + bOff + (uint32_t)((ntp * 16 * SAST) * 2) + kkB);
#pragma unroll
                for (int mt = 0; mt < 4; mt++) {
                    mma_f16(acc[mt][2 * ntp][0], acc[mt][2 * ntp][1],
                            acc[mt][2 * ntp][2], acc[mt][2 * ntp][3],
                            afr[mt][0], afr[mt][1], afr[mt][2], afr[mt][3],
                            b0, b1);
                    mma_f16(acc[mt][2 * ntp + 1][0], acc[mt][2 * ntp + 1][1],
                            acc[mt][2 * ntp + 1][2], acc[mt][2 * ntp + 1][3],
                            afr[mt][0], afr[mt][1], afr[mt][2], afr[mt][3],
                            b2, b3);
                }
            }
        }
    }

    // Epilogue: warp tile 64x32
#pragma unroll
    for (int mt = 0; mt < 4; mt++) {
        const int m0 = rowBase + warp_m * 64 + mt * 16;
#pragma unroll
        for (int nt = 0; nt < 4; nt++) {
            const int n0 = colBase + warp_n * 32 + nt * 8;
            if (outHalf) {
                *(__half2*)(Ch + (size_t)(m0 + g) * N + n0 + 2 * q) =
                    __floats2half2_rn(acc[mt][nt][0], acc[mt][nt][1]);
                *(__half2*)(Ch + (size_t)(m0 + g + 8) * N + n0 + 2 * q) =
                    __floats2half2_rn(acc[mt][nt][2], acc[mt][nt][3]);
            } else {
                *(float2*)(Cf + (size_t)(m0 + g) * N + n0 + 2 * q) =
                    make_float2(acc[mt][nt][0], acc[mt][nt][1]);
                *(float2*)(Cf + (size_t)(m0 + g + 8) * N + n0 + 2 * q) =
                    make_float2(acc[mt][nt][2], acc[mt][nt][3]);
            }
        }
    }
}

// ===========================================================================
// fp16 tensor-core flash attention (unchanged from R14).
// ===========================================================================
#define FQ 128
#define FKT 64
#define QSTH 136
#define PSTH 72
#define KVBUF (FKT * QSTH)

#define FLASH_SMEM_BYTES ((FQ * QSTH + 4 * KVBUF + FQ * PSTH) * 2 + 2 * FKT * 4)

__global__ __launch_bounds__(256, 1) void flash_attn_f16(
    const __half* __restrict__ qkv, const int* __restrict__ mask,
    __half* __restrict__ y)
{
    extern __shared__ __half smh[];
    __half* Qs = smh;                          // FQ x QSTH
    __half* Ks = Qs + FQ * QSTH;               // 2 x KVBUF
    __half* Vs = Ks + 2 * KVBUF;               // 2 x KVBUF
    __half* Ps = Vs + 2 * KVBUF;               // FQ x PSTH
    float* bias = (float*)(Ps + FQ * PSTH);    // [2][FKT]

    const int qt = blockIdx.x;
    const int bh = blockIdx.y;
    const int b = bh / CH;
    const int h = bh % CH;

    const int tid = threadIdx.x;
    const int wid = tid >> 5;
    const int lane = tid & 31;
    const int g = lane >> 2;
    const int q = lane & 3;
    const int m0 = wid * 16;

    const size_t baseQ = (size_t)b * CT * QKVD + (size_t)h * CHD;
    const size_t baseK = baseQ + CD;
    const size_t baseV = baseQ + 2 * CD;
    const int q0 = qt * FQ;

    const uint32_t qSm = (uint32_t)__cvta_generic_to_shared(Qs);
    const uint32_t kSm = (uint32_t)__cvta_generic_to_shared(Ks);
    const uint32_t vSm = (uint32_t)__cvta_generic_to_shared(Vs);
    const uint32_t pSm = (uint32_t)__cvta_generic_to_shared(Ps);

    const uint32_t aQ = qSm + a_off16(lane, QSTH) + (uint32_t)(m0 * QSTH * 2);
    const uint32_t bK = kSm + b_off16(lane, QSTH);
    const uint32_t aP = pSm + a_off16(lane, PSTH) + (uint32_t)(m0 * PSTH * 2);
    const uint32_t tV = vSm + a_off16(lane, QSTH);

    const int krow = tid >> 4;            // 0..15
    const int kc = (tid & 15) * 8;        // halves

    // Q tile
    {
#pragma unroll
        for (int p = 0; p < 8; p++) {
            int r = krow + p * 16;
            cp16(qSm + (uint32_t)((r * QSTH + kc) * 2),
                 qkv + baseQ + (size_t)(q0 + r) * QKVD + kc);
        }
        cp_commit();
    }

    auto issueKV = [&](int ti) {
        const int kt0 = ti * FKT;
        const int buf = ti & 1;
        const uint32_t kB = kSm + (uint32_t)(buf * KVBUF * 2);
        const uint32_t vB = vSm + (uint32_t)(buf * KVBUF * 2);
#pragma unroll
        for (int p = 0; p < 4; p++) {
            int r = krow + p * 16;
            cp16(kB + (uint32_t)((r * QSTH + kc) * 2),
                 qkv + baseK + (size_t)(kt0 + r) * QKVD + kc);
            cp16(vB + (uint32_t)((r * QSTH + kc) * 2),
                 qkv + baseV + (size_t)(kt0 + r) * QKVD + kc);
        }
        if (tid < FKT)
            bias[buf * FKT + tid] = mask[b * CT + kt0 + tid] ? 0.0f : -1e30f;
        cp_commit();
    };

    issueKV(0);

    float acc[16][4];
#pragma unroll
    for (int nt = 0; nt < 16; nt++)
#pragma unroll
        for (int c = 0; c < 4; c++) acc[nt][c] = 0.0f;
    float m_r0 = -1e30f, m_r1 = -1e30f;
    float l_r0 = 0.0f, l_r1 = 0.0f;

    const float cs = 0.08838834764831845f * 1.4426950408889634f;
    const int ntiles = CT / FKT;

    for (int ti = 0; ti < ntiles; ti++) {
        cp_wait<0>();
        __syncthreads();
        if (ti + 1 < ntiles) issueKV(ti + 1);

        const int buf = ti & 1;
        const uint32_t kOff = (uint32_t)(buf * KVBUF * 2);
        const float* bb = bias + buf * FKT;

        // ---- S = Q @ K^T ----
        float s[8][4];
#pragma unroll
        for (int nt = 0; nt < 8; nt++)
#pragma unroll
            for (int c = 0; c < 4; c++) s[nt][c] = 0.0f;

#pragma unroll
        for (int ks = 0; ks < 8; ks++) {
            const uint32_t kkB = (uint32_t)(ks * 16 * 2);
            uint32_t a0, a1, a2, a3;
            ldsm_x4(a0, a1, a2, a3, aQ + kkB);
#pragma unroll
            for (int ntp = 0; ntp < 4; ntp++) {
                uint32_t b0, b1, b2, b3;
                ldsm_x4(b0, b1, b2, b3,
                        bK + kOff + (uint32_t)(ntp * 16 * QSTH * 2) + kkB);
                mma_f16(s[2 * ntp][0], s[2 * ntp][1],
                        s[2 * ntp][2], s[2 * ntp][3],
                        a0, a1, a2, a3, b0, b1);
                mma_f16(s[2 * ntp + 1][0], s[2 * ntp + 1][1],
                        s[2 * ntp + 1][2], s[2 * ntp + 1][3],
                        a0, a1, a2, a3, b2, b3);
            }
        }

#pragma unroll
        for (int nt = 0; nt < 8; nt++) {
            float2 bv = *(const float2*)&bb[nt * 8 + 2 * q];
            s[nt][0] = fmaf(s[nt][0], cs, bv.x);
            s[nt][1] = fmaf(s[nt][1], cs, bv.y);
            s[nt][2] = fmaf(s[nt][2], cs, bv.x);
            s[nt][3] = fmaf(s[nt][3], cs, bv.y);
        }

        float tm0 = -1e30f, tm1 = -1e30f;
#pragma unroll
        for (int nt = 0; nt < 8; nt++) {
            tm0 = fmaxf(tm0, fmaxf(s[nt][0], s[nt][1]));
            tm1 = fmaxf(tm1, fmaxf(s[nt][2], s[nt][3]));
        }
        tm0 = fmaxf(tm0, __shfl_xor_sync(0xffffffffu, tm0, 1));
        tm0 = fmaxf(tm0, __shfl_xor_sync(0xffffffffu, tm0, 2));
        tm1 = fmaxf(tm1, __shfl_xor_sync(0xffffffffu, tm1, 1));
        tm1 = fmaxf(tm1, __shfl_xor_sync(0xffffffffu, tm1, 2));

        const float mn0 = fmaxf(m_r0, tm0);
        const float mn1 = fmaxf(m_r1, tm1);
        const float corr0 = ex2(m_r0 - mn0);
        const float corr1 = ex2(m_r1 - mn1);
        m_r0 = mn0; m_r1 = mn1;

        float ps0 = 0.0f, ps1 = 0.0f;
#pragma unroll
        for (int nt = 0; nt < 8; nt++) {
            float p0 = ex2(s[nt][0] - mn0);
            float p1 = ex2(s[nt][1] - mn0);
            float p2 = ex2(s[nt][2] - mn1);
            float p3 = ex2(s[nt][3] - mn1);
            ps0 += p0 + p1;
            ps1 += p2 + p3;
            *(__half2*)&Ps[(m0 + g) * PSTH + nt * 8 + 2 * q] =
                __floats2half2_rn(p0, p1);
            *(__half2*)&Ps[(m0 + g + 8) * PSTH + nt * 8 + 2 * q] =
                __floats2half2_rn(p2, p3);
        }
        ps0 += __shfl_xor_sync(0xffffffffu, ps0, 1);
        ps0 += __shfl_xor_sync(0xffffffffu, ps0, 2);
        ps1 += __shfl_xor_sync(0xffffffffu, ps1, 1);
        ps1 += __shfl_xor_sync(0xffffffffu, ps1, 2);
        l_r0 = l_r0 * corr0 + ps0;
        l_r1 = l_r1 * corr1 + ps1;

#pragma unroll
        for (int nt = 0; nt < 16; nt++) {
            acc[nt][0] *= corr0; acc[nt][1] *= corr0;
            acc[nt][2] *= corr1; acc[nt][3] *= corr1;
        }
        __syncwarp();

        // ---- O += P @ V ----
#pragma unroll
        for (int ks = 0; ks < 4; ks++) {
            uint32_t a0, a1, a2, a3;
            ldsm_x4(a0, a1, a2, a3, aP + (uint32_t)(ks * 16 * 2));
#pragma unroll
            for (int ntp = 0; ntp < 8; ntp++) {
                uint32_t b0, b1, b2, b3;
                ldsm_x4_trans(b0, b1, b2, b3,
                              tV + kOff
                              + (uint32_t)((ks * 16 * QSTH + ntp * 16) * 2));
                mma_f16(acc[2 * ntp][0], acc[2 * ntp][1],
                        acc[2 * ntp][2], acc[2 * ntp][3],
                        a0, a1, a2, a3, b0, b1);
                mma_f16(acc[2 * ntp + 1][0], acc[2 * ntp + 1][1],
                        acc[2 * ntp + 1][2], acc[2 * ntp + 1][3],
                        a0, a1, a2, a3, b2, b3);
            }
        }
    }

    const float inv0 = 1.0f / l_r0;
    const float inv1 = 1.0f / l_r1;
    const int row0 = q0 + m0 + g;
    const int row1 = row0 + 8;
    __half* y0 = y + (size_t)(b * CT + row0) * CD + h * CHD;
    __half* y1 = y + (size_t)(b * CT + row1) * CD + h * CHD;
#pragma unroll
    for (int nt = 0; nt < 16; nt++) {
        const int col = nt * 8 + 2 * q;
        *(__half2*)(y0 + col) =
            __floats2half2_rn(acc[nt][0] * inv0, acc[nt][1] * inv0);
        *(__half2*)(y1 + col) =
            __floats2half2_rn(acc[nt][2] * inv1, acc[nt][3] * inv1);
    }
}

// ---------------------------------------------------------------------------
extern "C" void kernel_launch(void* const* d_in, const int* in_sizes, int n_in,
                              void* d_out, int out_size)
{
    const float* x      = (const float*)d_in[0];
    const int*   mask   = (const int*)d_in[1];
    const float* w_qkv  = (const float*)d_in[2];
    const float* w_o    = (const float*)d_in[3];
    float*       out    = (float*)d_out;

    __half *qkv = nullptr, *y = nullptr, *xh = nullptr, *wqkvh = nullptr, *woh = nullptr;
    cudaGetSymbolAddress((void**)&qkv, g_qkv);
    cudaGetSymbolAddress((void**)&y, g_y);
    cudaGetSymbolAddress((void**)&xh, g_xh);
    cudaGetSymbolAddress((void**)&wqkvh, g_wqkvh);
    cudaGetSymbolAddress((void**)&woh, g_woh);

    cudaFuncSetAttribute(hgemm_tc,
                         cudaFuncAttributeMaxDynamicSharedMemorySize,
                         SGEMM_SMEM_BYTES);
    cudaFuncSetAttribute(flash_attn_f16,
                         cudaFuncAttributeMaxDynamicSharedMemorySize,
                         FLASH_SMEM_BYTES);

    // 0) Convert inputs to fp16
    {
        int n4x = (CB * CT * CD) / 4;
        int n4w = (QKVD * CD) / 4;
        int n4o = (CD * CD) / 4;
        f32_to_f16_kernel<<<(n4x + 255) / 256, 256>>>((const float4*)x, (__half2*)xh, n4x);
        f32_to_f16_kernel<<<(n4w + 255) / 256, 256>>>((const float4*)w_qkv, (__half2*)wqkvh, n4w);
        f32_to_f16_kernel<<<(n4o + 255) / 256, 256>>>((const float4*)w_o, (__half2*)woh, n4o);
    }

    // 1) qkv = xh @ wqkvh^T : M=8192, N=6144, K=2048 (fp16 out)
    {
        dim3 grid(QKVD / 256, (CB * CT) / 128);
        hgemm_tc<<<grid, GTHREADS, SGEMM_SMEM_BYTES>>>(
            xh, wqkvh, nullptr, qkv, CB * CT, QKVD, CD, 1);
    }

    // 2) fused attention -> y (fp16)
    {
        dim3 grid(CT / FQ, CB * CH);
        flash_attn_f16<<<grid, 256, FLASH_SMEM_BYTES>>>(qkv, mask, y);
    }

    // 3) out = y @ woh^T : M=8192, N=2048, K=2048 (fp32 out)
    {
        dim3 grid(CD / 256, (CB * CT) / 128);
        hgemm_tc<<<grid, GTHREADS, SGEMM_SMEM_BYTES>>>(
            y, woh, out, nullptr, CB * CT, CD, CD, 0);
    }
}